// round 8
// baseline (speedup 1.0000x reference)
#include <cuda_runtime.h>
#include <cuda_bf16.h>
#include <math.h>

// ---------------------------------------------------------------------------
// GritLM pooling: masked segment mean over tokens + L2 normalize per sequence.
// Inputs (metadata order):
//   d_in[0] : float32 hidden_states [TOTAL, D]
//   d_in[1] : int32   prompt_lens   [B]
//   d_in[2] : int32   instruction_lens [B]
// Output: float32 [B, D]
//
// Stage 1: masked partial column sums (at the HBM wall, ~6.3 TB/s). Untouched.
// Stage 2: chunk-parallel reduce (nx*B CTAs) -> mean -> per-chunk ssq ->
//          last-CTA-per-row norm + rescale. Deterministic (fixed-order ssq
//          sum, no float atomics); counters reset by consumer (graph-safe).
// ---------------------------------------------------------------------------

#define TSPLIT 16
#define MAX_B  64
#define MAX_D  8192
#define MAX_NX 8
// Static device scratch (runtime allocs forbidden). Zero-initialized at load.
__device__ float g_part[(size_t)TSPLIT * MAX_B * MAX_D];
__device__ float g_ssq [(size_t)MAX_B * MAX_NX];
__device__ int   g_cnt [(size_t)MAX_B];

__device__ __forceinline__ float4 ldcs4(const float* p) {
    return __ldcs((const float4*)p);
}

// ---------------------------------------------------------------------------
// Kernel 1: partial masked column sums.
// grid: (ceil(D/1024), B, TSPLIT), block: 256 threads, 32 regs -> 8 CTA/SM,
// 1024 CTAs = one full wave. 8x row unroll -> MLP=8 LDG.128 per thread.
// ---------------------------------------------------------------------------
__global__ __launch_bounds__(256, 8)
void pool_partial_kernel(const float* __restrict__ hs,
                         const int* __restrict__ plen,
                         const int* __restrict__ ilen,
                         int B, int D)
{
    const int b     = blockIdx.y;
    const int split = blockIdx.z;
    const int c0    = blockIdx.x * 1024 + threadIdx.x * 4;

    long long start = 0;
    for (int i = 0; i < b; i++) start += (long long)plen[i];
    const int len  = plen[b];
    const int inst = ilen[b];

    const int chunk = (len + TSPLIT - 1) / TSPLIT;
    int r0 = split * chunk;
    int r1 = r0 + chunk; if (r1 > len) r1 = len;
    if (r0 < inst) r0 = inst;        // mask instruction tokens

    float4 acc0 = make_float4(0.f, 0.f, 0.f, 0.f);
    float4 acc1 = make_float4(0.f, 0.f, 0.f, 0.f);

    if (c0 < D && r0 < r1) {
        const float* base = hs + (start + (long long)r0) * (long long)D + c0;
        const long long stride = D;
        int r = r0;
        for (; r + 7 < r1; r += 8) {     // MLP=8 independent LDG.128
            float4 v0 = ldcs4(base);
            float4 v1 = ldcs4(base + stride);
            float4 v2 = ldcs4(base + 2 * stride);
            float4 v3 = ldcs4(base + 3 * stride);
            float4 v4 = ldcs4(base + 4 * stride);
            float4 v5 = ldcs4(base + 5 * stride);
            float4 v6 = ldcs4(base + 6 * stride);
            float4 v7 = ldcs4(base + 7 * stride);
            acc0.x += v0.x + v1.x + v2.x + v3.x;
            acc0.y += v0.y + v1.y + v2.y + v3.y;
            acc0.z += v0.z + v1.z + v2.z + v3.z;
            acc0.w += v0.w + v1.w + v2.w + v3.w;
            acc1.x += v4.x + v5.x + v6.x + v7.x;
            acc1.y += v4.y + v5.y + v6.y + v7.y;
            acc1.z += v4.z + v5.z + v6.z + v7.z;
            acc1.w += v4.w + v5.w + v6.w + v7.w;
            base += 8 * stride;
        }
        for (; r < r1; r++) {
            float4 v = ldcs4(base);
            acc0.x += v.x; acc0.y += v.y; acc0.z += v.z; acc0.w += v.w;
            base += stride;
        }
    }

    if (c0 < D) {
        acc0.x += acc1.x; acc0.y += acc1.y; acc0.z += acc1.z; acc0.w += acc1.w;
        float* p = &g_part[((size_t)split * B + b) * (size_t)D + c0];
        *(float4*)p = acc0;
    }

    // Let the dependent (PDL) kernel start as soon as possible.
    cudaTriggerProgrammaticLaunchCompletion();
}

// ---------------------------------------------------------------------------
// Kernel 2 (PDL): chunk-parallel reduce + mean + L2 normalize.
// grid: (nx, B), block: 256 threads; each CTA owns a 1024-float chunk of one
// row. Last CTA per row combines per-chunk ssq (fixed order) and rescales.
// ---------------------------------------------------------------------------
__global__ __launch_bounds__(256)
void mean_norm_kernel(const int* __restrict__ plen,
                      const int* __restrict__ ilen,
                      float* __restrict__ out,
                      int B, int D)
{
    const int x  = blockIdx.x;
    const int b  = blockIdx.y;
    const int nx = gridDim.x;
    const int c0 = x * 1024 + threadIdx.x * 4;

    // k1-independent prologue (overlaps k1 tail under PDL)
    const float inv = 1.0f / (float)(plen[b] - ilen[b]);

    cudaGridDependencySynchronize();

    // ---- chunk reduce: sum TSPLIT partials, scale to mean, store -----------
    float4 s = make_float4(0.f, 0.f, 0.f, 0.f);
    if (c0 < D) {
#pragma unroll
        for (int t = 0; t < TSPLIT; t++) {
            const float4 v = *(const float4*)&g_part[((size_t)t * B + b) * (size_t)D + c0];
            s.x += v.x; s.y += v.y; s.z += v.z; s.w += v.w;
        }
        s.x *= inv; s.y *= inv; s.z *= inv; s.w *= inv;
        *(float4*)(out + (size_t)b * D + c0) = s;   // unnormalized mean
    }

    // ---- per-chunk sum of squares (block reduce, 8 warps) -------------------
    float ss = s.x * s.x + s.y * s.y + s.z * s.z + s.w * s.w;
    __shared__ float sm[8];
    for (int off = 16; off > 0; off >>= 1)
        ss += __shfl_down_sync(0xFFFFFFFFu, ss, off);
    const int lane = threadIdx.x & 31, wid = threadIdx.x >> 5;
    if (lane == 0) sm[wid] = ss;
    __syncthreads();
    if (wid == 0) {
        float v = (lane < 8) ? sm[lane] : 0.f;
        for (int off = 4; off > 0; off >>= 1)
            v += __shfl_down_sync(0xFFFFFFFFu, v, off);
        if (lane == 0) sm[0] = v;
    }
    __syncthreads();

    // ---- handoff: last CTA of row b does the norm ---------------------------
    __shared__ int s_role;
    if (threadIdx.x == 0) {
        g_ssq[b * nx + x] = sm[0];
        __threadfence();                         // publish mean chunk + ssq
        int v = atomicAdd(&g_cnt[b], 1);
        s_role = (v == nx - 1);
    }
    __syncthreads();
    if (!s_role) return;

    if (threadIdx.x == 0) g_cnt[b] = 0;          // reset for next graph replay
    __threadfence();                             // acquire other chunks' data

    float tot = 0.f;
    for (int xi = 0; xi < nx; xi++)              // fixed order: deterministic
        tot += g_ssq[b * nx + xi];
    const float inv_n = 1.0f / fmaxf(sqrtf(tot), 1e-12f);

    // rescale full row b (L2-hot: just written by the nx CTAs)
    for (int c = threadIdx.x * 4; c < D; c += 1024) {
        float4 v = *(const float4*)(out + (size_t)b * D + c);
        v.x *= inv_n; v.y *= inv_n; v.z *= inv_n; v.w *= inv_n;
        *(float4*)(out + (size_t)b * D + c) = v;
    }
}

// ---------------------------------------------------------------------------
extern "C" void kernel_launch(void* const* d_in, const int* in_sizes, int n_in,
                              void* d_out, int out_size)
{
    const float* hs   = (const float*)d_in[0];
    const int*   plen = (const int*)d_in[1];
    const int*   ilen = (const int*)d_in[2];
    float*       out  = (float*)d_out;

    const int B = in_sizes[1];
    const int D = out_size / B;   // 4096
    const int nx = (D + 1023) / 1024;

    // Stage 1: partial sums (memory-wall bound)
    dim3 grid1(nx, B, TSPLIT);
    pool_partial_kernel<<<grid1, 256>>>(hs, plen, ilen, B, D);

    // Stage 2: chunk-parallel reduce + mean + L2 normalize, PDL-overlapped.
    cudaLaunchConfig_t cfg = {};
    cfg.gridDim  = dim3(nx, B, 1);
    cfg.blockDim = dim3(256, 1, 1);
    cfg.dynamicSmemBytes = 0;
    cfg.stream = 0;
    cudaLaunchAttribute attrs[1];
    attrs[0].id = cudaLaunchAttributeProgrammaticStreamSerialization;
    attrs[0].val.programmaticStreamSerializationAllowed = 1;
    cfg.attrs = attrs;
    cfg.numAttrs = 1;
    cudaLaunchKernelEx(&cfg, mean_norm_kernel, plen, ilen, out, B, D);
}

// round 9
// speedup vs baseline: 1.0695x; 1.0695x over previous
#include <cuda_runtime.h>
#include <cuda_bf16.h>
#include <math.h>

// ---------------------------------------------------------------------------
// GritLM pooling: masked segment mean over tokens + L2 normalize per sequence.
// Inputs (metadata order):
//   d_in[0] : float32 hidden_states [TOTAL, D]
//   d_in[1] : int32   prompt_lens   [B]
//   d_in[2] : int32   instruction_lens [B]
// Output: float32 [B, D]
//
// Stage 1: one CTA (1024 threads) owns full rows of one sequence chunk ->
//          perfectly contiguous DRAM streams (16 KB/row, multi-MB per CTA).
//          144 CTAs = single wave. Each thread keeps ONE float4 accumulator.
// Stage 2: fused reduce + mean + L2 normalize (16 CTAs, PDL, no atomics).
// ---------------------------------------------------------------------------

#define TSPLIT 9
#define MAX_B  64
#define MAX_D  8192
// Static device scratch (runtime allocs forbidden).
__device__ float g_part[(size_t)TSPLIT * MAX_B * MAX_D];

__device__ __forceinline__ float4 ldcs4(const float* p) {
    return __ldcs((const float4*)p);
}

// ---------------------------------------------------------------------------
// Kernel 1: contiguous-row partial sums.
// grid: (TSPLIT, B), block: 1024 threads. Thread t owns column t*4..t*4+3.
// 8x row unroll -> 8 outstanding LDG.128 per thread; rows are contiguous so
// each CTA is one long sequential stream.
// ---------------------------------------------------------------------------
__global__ __launch_bounds__(1024, 1)
void pool_partial_kernel(const float* __restrict__ hs,
                         const int* __restrict__ plen,
                         const int* __restrict__ ilen,
                         int B, int D)
{
    const int split = blockIdx.x;
    const int b     = blockIdx.y;
    const int c     = threadIdx.x * 4;

    long long start = 0;
    for (int i = 0; i < b; i++) start += (long long)plen[i];
    const int len  = plen[b];
    const int inst = ilen[b];

    const int chunk = (len + TSPLIT - 1) / TSPLIT;
    int r0 = split * chunk;
    int r1 = r0 + chunk; if (r1 > len) r1 = len;
    if (r0 < inst) r0 = inst;        // mask instruction tokens

    float4 acc = make_float4(0.f, 0.f, 0.f, 0.f);

    if (c < D && r0 < r1) {
        const float* base = hs + (start + (long long)r0) * (long long)D + c;
        const long long stride = D;
        int r = r0;
        for (; r + 7 < r1; r += 8) {     // MLP=8; rows contiguous in DRAM
            float4 v0 = ldcs4(base);
            float4 v1 = ldcs4(base + stride);
            float4 v2 = ldcs4(base + 2 * stride);
            float4 v3 = ldcs4(base + 3 * stride);
            float4 v4 = ldcs4(base + 4 * stride);
            float4 v5 = ldcs4(base + 5 * stride);
            float4 v6 = ldcs4(base + 6 * stride);
            float4 v7 = ldcs4(base + 7 * stride);
            float sx0 = v0.x + v1.x, sx1 = v2.x + v3.x, sx2 = v4.x + v5.x, sx3 = v6.x + v7.x;
            float sy0 = v0.y + v1.y, sy1 = v2.y + v3.y, sy2 = v4.y + v5.y, sy3 = v6.y + v7.y;
            float sz0 = v0.z + v1.z, sz1 = v2.z + v3.z, sz2 = v4.z + v5.z, sz3 = v6.z + v7.z;
            float sw0 = v0.w + v1.w, sw1 = v2.w + v3.w, sw2 = v4.w + v5.w, sw3 = v6.w + v7.w;
            acc.x += (sx0 + sx1) + (sx2 + sx3);
            acc.y += (sy0 + sy1) + (sy2 + sy3);
            acc.z += (sz0 + sz1) + (sz2 + sz3);
            acc.w += (sw0 + sw1) + (sw2 + sw3);
            base += 8 * stride;
        }
        for (; r < r1; r++) {
            float4 v = ldcs4(base);
            acc.x += v.x; acc.y += v.y; acc.z += v.z; acc.w += v.w;
            base += stride;
        }
    }

    if (c < D) {
        float* p = &g_part[((size_t)split * B + b) * (size_t)D + c];
        *(float4*)p = acc;
    }

    // Let the dependent (PDL) kernel start as soon as possible.
    cudaTriggerProgrammaticLaunchCompletion();
}

// ---------------------------------------------------------------------------
// Kernel 2 (fused, PDL): reduce TSPLIT partials -> mean -> L2 normalize.
// One block per sequence; blockDim.x == D/4 (one float4 per thread).
// ---------------------------------------------------------------------------
__global__ __launch_bounds__(1024)
void mean_norm_kernel(const int* __restrict__ plen,
                      const int* __restrict__ ilen,
                      float* __restrict__ out,
                      int B, int D)
{
    const int b = blockIdx.x;
    const int c = threadIdx.x * 4;

    // k1-independent prologue (overlaps k1 tail under PDL)
    const float inv = 1.0f / (float)(plen[b] - ilen[b]);
    const float* pp = &g_part[(size_t)b * D + c];

    cudaGridDependencySynchronize();

    float4 s = make_float4(0.f, 0.f, 0.f, 0.f);
    if (c < D) {
#pragma unroll
        for (int t = 0; t < TSPLIT; t++) {
            const float4 v = *(const float4*)(pp + (size_t)t * B * D);
            s.x += v.x; s.y += v.y; s.z += v.z; s.w += v.w;
        }
        s.x *= inv; s.y *= inv; s.z *= inv; s.w *= inv;
    }

    // block-reduce sum of squares of the mean vector
    float ss = s.x * s.x + s.y * s.y + s.z * s.z + s.w * s.w;
    __shared__ float sm[32];
    for (int off = 16; off > 0; off >>= 1)
        ss += __shfl_down_sync(0xFFFFFFFFu, ss, off);
    const int lane = threadIdx.x & 31, wid = threadIdx.x >> 5;
    if (lane == 0) sm[wid] = ss;
    __syncthreads();
    const int nwarps = (blockDim.x + 31) >> 5;
    if (wid == 0) {
        float v = (lane < nwarps) ? sm[lane] : 0.f;
        for (int off = 16; off > 0; off >>= 1)
            v += __shfl_down_sync(0xFFFFFFFFu, v, off);
        if (lane == 0) sm[0] = v;
    }
    __syncthreads();

    const float norm = fmaxf(sqrtf(sm[0]), 1e-12f);
    const float inv_n = 1.0f / norm;

    if (c < D) {
        s.x *= inv_n; s.y *= inv_n; s.z *= inv_n; s.w *= inv_n;
        *(float4*)(out + (size_t)b * D + c) = s;
    }
}

// ---------------------------------------------------------------------------
extern "C" void kernel_launch(void* const* d_in, const int* in_sizes, int n_in,
                              void* d_out, int out_size)
{
    const float* hs   = (const float*)d_in[0];
    const int*   plen = (const int*)d_in[1];
    const int*   ilen = (const int*)d_in[2];
    float*       out  = (float*)d_out;

    const int B = in_sizes[1];
    const int D = out_size / B;   // 4096

    // Stage 1: contiguous-row partial sums (144 CTAs = one wave).
    dim3 grid1(TSPLIT, B);
    pool_partial_kernel<<<grid1, 1024>>>(hs, plen, ilen, B, D);

    // Stage 2: fused reduce + mean + L2 normalize, PDL-overlapped.
    int threads = D / 4;            // 1024 for D=4096
    if (threads > 1024) threads = 1024;

    cudaLaunchConfig_t cfg = {};
    cfg.gridDim  = dim3(B, 1, 1);
    cfg.blockDim = dim3(threads, 1, 1);
    cfg.dynamicSmemBytes = 0;
    cfg.stream = 0;
    cudaLaunchAttribute attrs[1];
    attrs[0].id = cudaLaunchAttributeProgrammaticStreamSerialization;
    attrs[0].val.programmaticStreamSerializationAllowed = 1;
    cfg.attrs = attrs;
    cfg.numAttrs = 1;
    cudaLaunchKernelEx(&cfg, mean_norm_kernel, plen, ilen, out, B, D);
}